// round 13
// baseline (speedup 1.0000x reference)
#include <cuda_runtime.h>
#include <cuda_bf16.h>
#include <math_constants.h>
#include <cstdint>

#define BB 16
#define SS 512
#define DD 256
#define HH 16
#define HD 16
#define TD 768

typedef unsigned long long ull;

__device__ float g_qkv[BB * SS * TD];   // scratch qkv [B*S, 3D]
__device__ float g_av[BB * DD];
__device__ float g_h1[BB * DD];
__device__ float g_h2[BB * DD];

// bf16 split-precision operands for tensor-core qkv
__device__ __nv_bfloat16 g_xhi[BB * SS * DD];
__device__ __nv_bfloat16 g_xlo[BB * SS * DD];
__device__ __nv_bfloat16 g_whi[TD * DD];
__device__ __nv_bfloat16 g_wlo[TD * DD];

__device__ __forceinline__ ull pack2(float x, float y) {
    ull r; asm("mov.b64 %0, {%1, %2};" : "=l"(r) : "f"(x), "f"(y)); return r;
}
__device__ __forceinline__ void unpack2(ull v, float& x, float& y) {
    asm("mov.b64 {%0, %1}, %2;" : "=f"(x), "=f"(y) : "l"(v));
}
__device__ __forceinline__ ull fma2(ull a, ull b, ull c) {
    ull d; asm("fma.rn.f32x2 %0, %1, %2, %3;" : "=l"(d) : "l"(a), "l"(b), "l"(c)); return d;
}
__device__ __forceinline__ uint32_t smem_u32(const void* p) {
    uint32_t a;
    asm("{ .reg .u64 t; cvta.to.shared.u64 t, %1; cvt.u32.u64 %0, t; }" : "=r"(a) : "l"(p));
    return a;
}

// ---------------------------------------------------------------------------
// Prep: convert x = news+pos and w to bf16 hi/lo pairs.
// ---------------------------------------------------------------------------
__global__ __launch_bounds__(256) void prep_kernel(
    const float* __restrict__ news,
    const float* __restrict__ pos,
    const float* __restrict__ w)
{
    const int row = blockIdx.x;
    const int t   = threadIdx.x;
    if (row < BB * SS) {
        float v = news[(size_t)row * DD + t] + pos[(size_t)(row & (SS - 1)) * DD + t];
        __nv_bfloat16 h = __float2bfloat16(v);
        float lo = v - __bfloat162float(h);
        g_xhi[(size_t)row * DD + t] = h;
        g_xlo[(size_t)row * DD + t] = __float2bfloat16(lo);
    } else {
        int r = row - BB * SS;
        float v = w[(size_t)r * DD + t];
        __nv_bfloat16 h = __float2bfloat16(v);
        float lo = v - __bfloat162float(h);
        g_whi[(size_t)r * DD + t] = h;
        g_wlo[(size_t)r * DD + t] = __float2bfloat16(lo);
    }
}

// ---------------------------------------------------------------------------
// qkv via warp-MMA bf16 (m16n8k16, HMMA), split-precision 3-pass.  (R12 WIN)
// ---------------------------------------------------------------------------
#define MMS 72
#define MAT_BYTES (128 * MMS * 2)
#define SMEM_MMA (4 * MAT_BYTES)

__device__ __forceinline__ void ldsm_x4(uint32_t (&r)[4], uint32_t addr) {
    asm volatile("ldmatrix.sync.aligned.m8n8.x4.shared.b16 {%0,%1,%2,%3}, [%4];"
                 : "=r"(r[0]), "=r"(r[1]), "=r"(r[2]), "=r"(r[3]) : "r"(addr));
}
__device__ __forceinline__ void ldsm_x2(uint32_t (&r)[2], uint32_t addr) {
    asm volatile("ldmatrix.sync.aligned.m8n8.x2.shared.b16 {%0,%1}, [%2];"
                 : "=r"(r[0]), "=r"(r[1]) : "r"(addr));
}
__device__ __forceinline__ void mma_bf16(float (&d)[4],
                                         const uint32_t (&a)[4],
                                         const uint32_t (&b)[2]) {
    asm volatile(
        "mma.sync.aligned.m16n8k16.row.col.f32.bf16.bf16.f32 "
        "{%0,%1,%2,%3}, {%4,%5,%6,%7}, {%8,%9}, {%0,%1,%2,%3};"
        : "+f"(d[0]), "+f"(d[1]), "+f"(d[2]), "+f"(d[3])
        : "r"(a[0]), "r"(a[1]), "r"(a[2]), "r"(a[3]), "r"(b[0]), "r"(b[1]));
}

__global__ __launch_bounds__(512) void qkv_mma_kernel(
    const float* __restrict__ bias, int row0)
{
    extern __shared__ __align__(16) char smem[];
    char* Ahi = smem;
    char* Alo = smem + MAT_BYTES;
    char* Bhi = smem + 2 * MAT_BYTES;
    char* Blo = smem + 3 * MAT_BYTES;

    const int t    = threadIdx.x;
    const int warp = t >> 5;
    const int lane = t & 31;
    const int wr   = warp >> 2;
    const int wc   = warp & 3;
    const int n0 = blockIdx.x * 128;
    const int m0 = row0 + blockIdx.y * 128;

    float acc[2][4][4];
#pragma unroll
    for (int i = 0; i < 2; i++)
#pragma unroll
        for (int j = 0; j < 4; j++)
#pragma unroll
            for (int f = 0; f < 4; f++) acc[i][j][f] = 0.f;

    const uint32_t sAhi = smem_u32(Ahi), sAlo = smem_u32(Alo);
    const uint32_t sBhi = smem_u32(Bhi), sBlo = smem_u32(Blo);

    for (int chunk = 0; chunk < 4; chunk++) {
        const int k0 = chunk * 64;
#pragma unroll
        for (int u = 0; u < 2; u++) {
            int idx = t * 2 + u;
            int row = idx >> 3;
            int seg = idx & 7;
            int soff = row * (MMS * 2) + seg * 16;
            const uint4* xh = reinterpret_cast<const uint4*>(
                g_xhi + (size_t)(m0 + row) * DD + k0 + seg * 8);
            const uint4* xl = reinterpret_cast<const uint4*>(
                g_xlo + (size_t)(m0 + row) * DD + k0 + seg * 8);
            const uint4* wh = reinterpret_cast<const uint4*>(
                g_whi + (size_t)(n0 + row) * DD + k0 + seg * 8);
            const uint4* wl = reinterpret_cast<const uint4*>(
                g_wlo + (size_t)(n0 + row) * DD + k0 + seg * 8);
            *reinterpret_cast<uint4*>(Ahi + soff) = *xh;
            *reinterpret_cast<uint4*>(Alo + soff) = *xl;
            *reinterpret_cast<uint4*>(Bhi + soff) = *wh;
            *reinterpret_cast<uint4*>(Blo + soff) = *wl;
        }
        __syncthreads();

#pragma unroll
        for (int ks = 0; ks < 4; ks++) {
            uint32_t ahi[2][4], alo[2][4];
#pragma unroll
            for (int i = 0; i < 2; i++) {
                uint32_t aoff = (uint32_t)((wr * 32 + 16 * i + (lane & 15)) * (MMS * 2)
                                           + ks * 32 + (lane >> 4) * 16);
                ldsm_x4(ahi[i], sAhi + aoff);
                ldsm_x4(alo[i], sAlo + aoff);
            }
#pragma unroll
            for (int j = 0; j < 4; j++) {
                uint32_t boff = (uint32_t)((wc * 32 + 8 * j + (lane & 7)) * (MMS * 2)
                                           + ks * 32 + ((lane >> 3) & 1) * 16);
                uint32_t bhi[2], blo[2];
                ldsm_x2(bhi, sBhi + boff);
                ldsm_x2(blo, sBlo + boff);
#pragma unroll
                for (int i = 0; i < 2; i++) {
                    mma_bf16(acc[i][j], ahi[i], bhi);
                    mma_bf16(acc[i][j], ahi[i], blo);
                    mma_bf16(acc[i][j], alo[i], bhi);
                }
            }
        }
        __syncthreads();
    }

    const int gm = m0 + wr * 32;
    const int gn = n0 + wc * 32;
#pragma unroll
    for (int i = 0; i < 2; i++) {
#pragma unroll
        for (int j = 0; j < 4; j++) {
            int r = gm + 16 * i + (lane >> 2);
            int c = gn + 8 * j + 2 * (lane & 3);
            float2 bv = *reinterpret_cast<const float2*>(bias + c);
            float2 v0 = {acc[i][j][0] + bv.x, acc[i][j][1] + bv.y};
            float2 v1 = {acc[i][j][2] + bv.x, acc[i][j][3] + bv.y};
            *reinterpret_cast<float2*>(g_qkv + (size_t)r * TD + c)       = v0;
            *reinterpret_cast<float2*>(g_qkv + (size_t)(r + 8) * TD + c) = v1;
        }
    }
}

// ---------------------------------------------------------------------------
// Kernel 2: scores + causal/pad mask + softmax -> attn_weights. (R9/R12 best)
// ---------------------------------------------------------------------------
__global__ __launch_bounds__(512) void attn_kernel(
    const unsigned char* __restrict__ mask,
    float* __restrict__ wout,
    int b0)
{
    __shared__ __align__(16) float Kt[HD][516];
    __shared__ __align__(16) ull   Qsu[64][HD];
    __shared__ __align__(4) unsigned char pm[SS];

    const int p = blockIdx.x;
    const int h = blockIdx.y;
    const int b = b0 + blockIdx.z;
    const int t = threadIdx.x;

    const int cA = p;
    const int cB = 7 - p;
    const int njbB  = ((cB + 1) * 64 + 127) >> 7;
    const int kmaxL = njbB << 7;

    const float* kbase = g_qkv + (size_t)b * SS * TD + DD + h * HD;
    for (int idx = t; idx < kmaxL * 4; idx += 512) {
        int key = idx >> 2;
        int dq  = (idx & 3) * 4;
        float4 kv = *reinterpret_cast<const float4*>(kbase + (size_t)key * TD + dq);
        Kt[dq + 0][key] = kv.x;
        Kt[dq + 1][key] = kv.y;
        Kt[dq + 2][key] = kv.z;
        Kt[dq + 3][key] = kv.w;
    }
    if (t < kmaxL) pm[t] = mask[b * SS + t];
    __syncthreads();

    const int wd    = t >> 5;
    const int lane  = t & 31;
    const int rbase = 4 * wd;

#pragma unroll
    for (int ci = 0; ci < 2; ci++) {
        const int qc  = (ci == 0) ? cA : cB;
        const int q0  = qc * 64;
        const int njb = ((qc + 1) * 64 + 127) >> 7;

        if (t < 256) {
            int row = t >> 2;
            int dq  = (t & 3) * 4;
            float4 qv = *reinterpret_cast<const float4*>(
                g_qkv + (size_t)(b * SS + q0 + row) * TD + h * HD + dq);
            Qsu[row][dq + 0] = pack2(qv.x, qv.x);
            Qsu[row][dq + 1] = pack2(qv.y, qv.y);
            Qsu[row][dq + 2] = pack2(qv.z, qv.z);
            Qsu[row][dq + 3] = pack2(qv.w, qv.w);
        }
        __syncthreads();

        ull s2[4][2][4];
#pragma unroll
        for (int r = 0; r < 4; r++)
#pragma unroll
            for (int pp = 0; pp < 2; pp++)
#pragma unroll
                for (int jb = 0; jb < 4; jb++) s2[r][pp][jb] = 0ULL;

#pragma unroll
        for (int d = 0; d < HD; d++) {
            ull q2[4];
#pragma unroll
            for (int r = 0; r < 4; r++) q2[r] = Qsu[rbase + r][d];
#pragma unroll
            for (int jb = 0; jb < 4; jb++) {
                if (jb < njb) {
                    ulonglong2 kp = *reinterpret_cast<const ulonglong2*>(
                        &Kt[d][4 * lane + 128 * jb]);
#pragma unroll
                    for (int r = 0; r < 4; r++) {
                        s2[r][0][jb] = fma2(q2[r], kp.x, s2[r][0][jb]);
                        s2[r][1][jb] = fma2(q2[r], kp.y, s2[r][1][jb]);
                    }
                }
            }
        }

#pragma unroll
        for (int r = 0; r < 4; r++) {
            const int rg = q0 + rbase + r;
            float v[16];
            float sum = 0.f;
#pragma unroll
            for (int jb = 0; jb < 4; jb++) {
                if (jb < njb) {
                    int kb = 4 * lane + 128 * jb;
                    uchar4 pmv = *reinterpret_cast<const uchar4*>(&pm[kb]);
                    float f0, f1, f2, f3;
                    unpack2(s2[r][0][jb], f0, f1);
                    unpack2(s2[r][1][jb], f2, f3);
                    float e0 = (kb + 0 > rg || pmv.x) ? 0.f : __expf(f0 * 0.25f);
                    float e1 = (kb + 1 > rg || pmv.y) ? 0.f : __expf(f1 * 0.25f);
                    float e2 = (kb + 2 > rg || pmv.z) ? 0.f : __expf(f2 * 0.25f);
                    float e3 = (kb + 3 > rg || pmv.w) ? 0.f : __expf(f3 * 0.25f);
                    v[jb * 4 + 0] = e0; v[jb * 4 + 1] = e1;
                    v[jb * 4 + 2] = e2; v[jb * 4 + 3] = e3;
                    sum += (e0 + e1) + (e2 + e3);
                }
            }
#pragma unroll
            for (int off = 16; off > 0; off >>= 1)
                sum += __shfl_xor_sync(0xffffffffu, sum, off);
            float inv = 1.f / sum;

            float4* orow = reinterpret_cast<float4*>(
                wout + (((size_t)(b * HH + h) * SS + rg) * SS));
#pragma unroll
            for (int jb = 0; jb < 4; jb++) {
                float4 o;
                if (jb < njb) {
                    o.x = v[jb * 4 + 0] * inv;
                    o.y = v[jb * 4 + 1] * inv;
                    o.z = v[jb * 4 + 2] * inv;
                    o.w = v[jb * 4 + 3] * inv;
                } else {
                    o.x = 0.f; o.y = 0.f; o.z = 0.f; o.w = 0.f;
                }
                __stcs(orow + lane + 32 * jb, o);
            }
        }
        __syncthreads();
    }
}

// ---------------------------------------------------------------------------
// Kernel 3a (NEW): attnv computes softmax(q_last·K^T/4)·V directly from qkv —
// no dependency on attn_weights. One block per (b,h), 256 threads.
// ---------------------------------------------------------------------------
__global__ __launch_bounds__(256) void attnv_kernel(
    const unsigned char* __restrict__ mask,
    int b0)
{
    __shared__ float esm[SS];
    __shared__ float qsm[HD];
    __shared__ float red[256];
    __shared__ int s_last;

    const int h = blockIdx.x;
    const int b = b0 + blockIdx.y;
    const int t = threadIdx.x;

    // last non-padded index
    int cnt = 0;
    for (int s = t; s < SS; s += 256) cnt += (mask[b * SS + s] == 0) ? 1 : 0;
    red[t] = (float)cnt;
    __syncthreads();
#pragma unroll
    for (int off = 128; off > 0; off >>= 1) {
        if (t < off) red[t] += red[t + off];
        __syncthreads();
    }
    if (t == 0) {
        int len = (int)(red[0] + 0.5f);
        s_last = (len > 0) ? (len - 1) : 0;
    }
    __syncthreads();
    const int last = s_last;

    // q row for position `last`
    if (t < HD)
        qsm[t] = g_qkv[(size_t)(b * SS + last) * TD + h * HD + t];
    __syncthreads();

    // scores + exp for keys t and t+256
    const float* kb = g_qkv + (size_t)b * SS * TD + DD + h * HD;
    float psum = 0.f;
#pragma unroll
    for (int u = 0; u < 2; u++) {
        int k = t + 256 * u;
        const float4* kr = reinterpret_cast<const float4*>(kb + (size_t)k * TD);
        float s = 0.f;
#pragma unroll
        for (int dq = 0; dq < 4; dq++) {
            float4 kv = kr[dq];
            s += qsm[dq * 4 + 0] * kv.x + qsm[dq * 4 + 1] * kv.y
               + qsm[dq * 4 + 2] * kv.z + qsm[dq * 4 + 3] * kv.w;
        }
        bool pad = (mask[b * SS + k] != 0);
        float e = (k > last || pad) ? 0.f : __expf(s * 0.25f);
        esm[k] = e;
        psum += e;
    }
    red[t] = psum;
    __syncthreads();
#pragma unroll
    for (int off = 128; off > 0; off >>= 1) {
        if (t < off) red[t] += red[t + off];
        __syncthreads();
    }
    const float inv = 1.f / red[0];
    __syncthreads();

    // av[d] = inv * sum_k e_k * V[k,d]
    const int d  = t & 15;
    const int kg = t >> 4;
    const float* vb = g_qkv + (size_t)b * SS * TD + 2 * DD + h * HD + d;
    float a0 = 0.f, a1 = 0.f;
#pragma unroll 8
    for (int j = 0; j < 32; j += 2) {
        int k0 = kg + 16 * j;
        int k1 = kg + 16 * (j + 1);
        a0 = fmaf(esm[k0], vb[(size_t)k0 * TD], a0);
        a1 = fmaf(esm[k1], vb[(size_t)k1 * TD], a1);
    }
    red[t] = a0 + a1;
    __syncthreads();
#pragma unroll
    for (int off = 128; off >= 16; off >>= 1) {
        if (t < off) red[t] += red[t + off];
        __syncthreads();
    }
    if (t < 16) g_av[b * DD + h * HD + t] = red[t] * inv;
}

// ---------------------------------------------------------------------------
// Kernel 3b/3c: y[b,j] = x[b,:] @ w[j,:] + bias[j]
// ---------------------------------------------------------------------------
__global__ __launch_bounds__(256) void mv_kernel(
    const float* __restrict__ x,
    const float* __restrict__ w,
    const float* __restrict__ bias,
    float* __restrict__ y,
    int b0)
{
    __shared__ __align__(16) float xs[DD];

    const int jc = blockIdx.x;
    const int b  = b0 + blockIdx.y;
    const int t  = threadIdx.x;
    const int wd = t >> 5, lane = t & 31;

    xs[t] = x[b * DD + t];
    __syncthreads();

    const float4* xp = reinterpret_cast<const float4*>(xs);
    float4 x0 = xp[lane * 2], x1 = xp[lane * 2 + 1];
#pragma unroll
    for (int jj = 0; jj < 4; jj++) {
        int j = jc * 32 + wd * 4 + jj;
        const float4* wr = reinterpret_cast<const float4*>(w + (size_t)j * DD);
        float4 w0 = wr[lane * 2], w1 = wr[lane * 2 + 1];
        float acc = x0.x * w0.x + x0.y * w0.y + x0.z * w0.z + x0.w * w0.w
                  + x1.x * w1.x + x1.y * w1.y + x1.z * w1.z + x1.w * w1.w;
#pragma unroll
        for (int off = 16; off > 0; off >>= 1)
            acc += __shfl_xor_sync(0xffffffffu, acc, off);
        if (lane == 0) y[b * DD + j] = acc + bias[j];
    }
}

// ---------------------------------------------------------------------------
// Kernel 3d: LN + ReLU + L2 normalize
// ---------------------------------------------------------------------------
__device__ __forceinline__ float block_reduce_sum(float v, float* red, int t) {
    red[t] = v;
    __syncthreads();
#pragma unroll
    for (int off = 128; off > 0; off >>= 1) {
        if (t < off) red[t] += red[t + off];
        __syncthreads();
    }
    float r = red[0];
    __syncthreads();
    return r;
}

__global__ __launch_bounds__(256) void ln_kernel(
    const float* __restrict__ lng, const float* __restrict__ lnb,
    float* __restrict__ user,
    int b0)
{
    __shared__ float red[256];
    const int b = b0 + blockIdx.x;
    const int t = threadIdx.x;

    float hv = g_h2[b * DD + t];
    float mu = block_reduce_sum(hv, red, t) * (1.0f / DD);
    float c  = hv - mu;
    float var = block_reduce_sum(c * c, red, t) * (1.0f / DD);
    float y = c * rsqrtf(var + 1e-5f) * lng[t] + lnb[t];
    y = fmaxf(y, 0.f);

    float ss = block_reduce_sum(y * y, red, t);
    float norm = sqrtf(ss);
    float denom = fmaxf(norm, 1e-12f);
    user[b * DD + t] = y / denom;
}

// ---------------------------------------------------------------------------
extern "C" void kernel_launch(void* const* d_in, const int* in_sizes, int n_in,
                              void* d_out, int out_size) {
    const float*         news  = (const float*)d_in[0];
    const unsigned char* mask  = (const unsigned char*)d_in[1];
    const float*         pos   = (const float*)d_in[2];
    const float*         inw   = (const float*)d_in[3];
    const float*         inb   = (const float*)d_in[4];
    const float*         outw  = (const float*)d_in[5];
    const float*         outb  = (const float*)d_in[6];
    const float*         projw = (const float*)d_in[7];
    const float*         projb = (const float*)d_in[8];
    const float*         lng   = (const float*)d_in[9];
    const float*         lnb   = (const float*)d_in[10];

    float* user = (float*)d_out;
    float* wout = (float*)d_out + (BB * DD);

    float* g_av_p;  cudaGetSymbolAddress((void**)&g_av_p,  g_av);
    float* g_h1_p;  cudaGetSymbolAddress((void**)&g_h1_p,  g_h1);
    float* g_h2_p;  cudaGetSymbolAddress((void**)&g_h2_p,  g_h2);

    static const int NSTREAM = 4;
    static cudaStream_t st[NSTREAM] = {};
    static cudaEvent_t evFork = nullptr;
    static cudaEvent_t evJoin[NSTREAM] = {};
    if (st[1] == nullptr) {
        for (int i = 1; i < NSTREAM; i++)
            cudaStreamCreateWithFlags(&st[i], cudaStreamNonBlocking);
        cudaEventCreateWithFlags(&evFork, cudaEventDisableTiming);
        for (int i = 1; i < NSTREAM; i++)
            cudaEventCreateWithFlags(&evJoin[i], cudaEventDisableTiming);
        cudaFuncSetAttribute(qkv_mma_kernel,
                             cudaFuncAttributeMaxDynamicSharedMemorySize, SMEM_MMA);
    }

    const int BPQ = BB / NSTREAM;          // 4 batches per stream
    const int QROWS = BPQ * SS;            // 2048 rows per quarter

    // bf16 hi/lo conversion (x and w) — before fork.
    prep_kernel<<<BB * SS + TD, 256>>>(news, pos, inw);

    cudaEventRecord(evFork, 0);
    for (int i = 1; i < NSTREAM; i++) cudaStreamWaitEvent(st[i], evFork, 0);

    for (int i = 0; i < NSTREAM; i++) {
        cudaStream_t s = (i == 0) ? (cudaStream_t)0 : st[i];
        int b0 = i * BPQ;
        dim3 qgrid(TD / 128, QROWS / 128);
        qkv_mma_kernel<<<qgrid, 512, SMEM_MMA, s>>>(inb, b0 * SS);

        // user-vector chain first (tiny, depends only on qkv)
        dim3 vgrid(HH, BPQ);
        attnv_kernel<<<vgrid, 256, 0, s>>>(mask, b0);
        dim3 mgrid(8, BPQ);
        mv_kernel<<<mgrid, 256, 0, s>>>(g_av_p, outw, outb, g_h1_p, b0);
        mv_kernel<<<mgrid, 256, 0, s>>>(g_h1_p, projw, projb, g_h2_p, b0);
        ln_kernel<<<BPQ, 256, 0, s>>>(lng, lnb, user, b0);

        // big attention-weights write last (stream tail)
        dim3 agrid(4, HH, BPQ);
        attn_kernel<<<agrid, 512, 0, s>>>(mask, wout, b0);
    }
    for (int i = 1; i < NSTREAM; i++) {
        cudaEventRecord(evJoin[i], st[i]);
        cudaStreamWaitEvent(0, evJoin[i], 0);
    }
}

// round 14
// speedup vs baseline: 1.0586x; 1.0586x over previous
#include <cuda_runtime.h>
#include <cuda_bf16.h>
#include <math_constants.h>
#include <cstdint>

#define BB 16
#define SS 512
#define DD 256
#define HH 16
#define HD 16
#define TD 768

typedef unsigned long long ull;

__device__ float g_qkv[BB * SS * TD];   // scratch qkv [B*S, 3D]
__device__ float g_av[BB * DD];
__device__ float g_h1[BB * DD];
__device__ float g_h2[BB * DD];

// bf16 split-precision operands for tensor-core qkv
__device__ __nv_bfloat16 g_xhi[BB * SS * DD];
__device__ __nv_bfloat16 g_xlo[BB * SS * DD];
__device__ __nv_bfloat16 g_whi[TD * DD];
__device__ __nv_bfloat16 g_wlo[TD * DD];

__device__ __forceinline__ ull pack2(float x, float y) {
    ull r; asm("mov.b64 %0, {%1, %2};" : "=l"(r) : "f"(x), "f"(y)); return r;
}
__device__ __forceinline__ void unpack2(ull v, float& x, float& y) {
    asm("mov.b64 {%0, %1}, %2;" : "=f"(x), "=f"(y) : "l"(v));
}
__device__ __forceinline__ ull fma2(ull a, ull b, ull c) {
    ull d; asm("fma.rn.f32x2 %0, %1, %2, %3;" : "=l"(d) : "l"(a), "l"(b), "l"(c)); return d;
}
__device__ __forceinline__ uint32_t smem_u32(const void* p) {
    uint32_t a;
    asm("{ .reg .u64 t; cvta.to.shared.u64 t, %1; cvt.u32.u64 %0, t; }" : "=r"(a) : "l"(p));
    return a;
}

// ---------------------------------------------------------------------------
// Prep: convert x = news+pos and w to bf16 hi/lo pairs.
// ---------------------------------------------------------------------------
__global__ __launch_bounds__(256) void prep_kernel(
    const float* __restrict__ news,
    const float* __restrict__ pos,
    const float* __restrict__ w)
{
    const int row = blockIdx.x;
    const int t   = threadIdx.x;
    if (row < BB * SS) {
        float v = news[(size_t)row * DD + t] + pos[(size_t)(row & (SS - 1)) * DD + t];
        __nv_bfloat16 h = __float2bfloat16(v);
        float lo = v - __bfloat162float(h);
        g_xhi[(size_t)row * DD + t] = h;
        g_xlo[(size_t)row * DD + t] = __float2bfloat16(lo);
    } else {
        int r = row - BB * SS;
        float v = w[(size_t)r * DD + t];
        __nv_bfloat16 h = __float2bfloat16(v);
        float lo = v - __bfloat162float(h);
        g_whi[(size_t)r * DD + t] = h;
        g_wlo[(size_t)r * DD + t] = __float2bfloat16(lo);
    }
}

// ---------------------------------------------------------------------------
// qkv via warp-MMA bf16 (m16n8k16, HMMA), split-precision 3-pass. (R12 WIN)
// ---------------------------------------------------------------------------
#define MMS 72
#define MAT_BYTES (128 * MMS * 2)
#define SMEM_MMA (4 * MAT_BYTES)

__device__ __forceinline__ void ldsm_x4(uint32_t (&r)[4], uint32_t addr) {
    asm volatile("ldmatrix.sync.aligned.m8n8.x4.shared.b16 {%0,%1,%2,%3}, [%4];"
                 : "=r"(r[0]), "=r"(r[1]), "=r"(r[2]), "=r"(r[3]) : "r"(addr));
}
__device__ __forceinline__ void ldsm_x2(uint32_t (&r)[2], uint32_t addr) {
    asm volatile("ldmatrix.sync.aligned.m8n8.x2.shared.b16 {%0,%1}, [%2];"
                 : "=r"(r[0]), "=r"(r[1]) : "r"(addr));
}
__device__ __forceinline__ void mma_bf16(float (&d)[4],
                                         const uint32_t (&a)[4],
                                         const uint32_t (&b)[2]) {
    asm volatile(
        "mma.sync.aligned.m16n8k16.row.col.f32.bf16.bf16.f32 "
        "{%0,%1,%2,%3}, {%4,%5,%6,%7}, {%8,%9}, {%0,%1,%2,%3};"
        : "+f"(d[0]), "+f"(d[1]), "+f"(d[2]), "+f"(d[3])
        : "r"(a[0]), "r"(a[1]), "r"(a[2]), "r"(a[3]), "r"(b[0]), "r"(b[1]));
}

__global__ __launch_bounds__(512) void qkv_mma_kernel(
    const float* __restrict__ bias, int row0)
{
    extern __shared__ __align__(16) char smem[];
    char* Ahi = smem;
    char* Alo = smem + MAT_BYTES;
    char* Bhi = smem + 2 * MAT_BYTES;
    char* Blo = smem + 3 * MAT_BYTES;

    const int t    = threadIdx.x;
    const int warp = t >> 5;
    const int lane = t & 31;
    const int wr   = warp >> 2;
    const int wc   = warp & 3;
    const int n0 = blockIdx.x * 128;
    const int m0 = row0 + blockIdx.y * 128;

    float acc[2][4][4];
#pragma unroll
    for (int i = 0; i < 2; i++)
#pragma unroll
        for (int j = 0; j < 4; j++)
#pragma unroll
            for (int f = 0; f < 4; f++) acc[i][j][f] = 0.f;

    const uint32_t sAhi = smem_u32(Ahi), sAlo = smem_u32(Alo);
    const uint32_t sBhi = smem_u32(Bhi), sBlo = smem_u32(Blo);

    for (int chunk = 0; chunk < 4; chunk++) {
        const int k0 = chunk * 64;
#pragma unroll
        for (int u = 0; u < 2; u++) {
            int idx = t * 2 + u;
            int row = idx >> 3;
            int seg = idx & 7;
            int soff = row * (MMS * 2) + seg * 16;
            const uint4* xh = reinterpret_cast<const uint4*>(
                g_xhi + (size_t)(m0 + row) * DD + k0 + seg * 8);
            const uint4* xl = reinterpret_cast<const uint4*>(
                g_xlo + (size_t)(m0 + row) * DD + k0 + seg * 8);
            const uint4* wh = reinterpret_cast<const uint4*>(
                g_whi + (size_t)(n0 + row) * DD + k0 + seg * 8);
            const uint4* wl = reinterpret_cast<const uint4*>(
                g_wlo + (size_t)(n0 + row) * DD + k0 + seg * 8);
            *reinterpret_cast<uint4*>(Ahi + soff) = *xh;
            *reinterpret_cast<uint4*>(Alo + soff) = *xl;
            *reinterpret_cast<uint4*>(Bhi + soff) = *wh;
            *reinterpret_cast<uint4*>(Blo + soff) = *wl;
        }
        __syncthreads();

#pragma unroll
        for (int ks = 0; ks < 4; ks++) {
            uint32_t ahi[2][4], alo[2][4];
#pragma unroll
            for (int i = 0; i < 2; i++) {
                uint32_t aoff = (uint32_t)((wr * 32 + 16 * i + (lane & 15)) * (MMS * 2)
                                           + ks * 32 + (lane >> 4) * 16);
                ldsm_x4(ahi[i], sAhi + aoff);
                ldsm_x4(alo[i], sAlo + aoff);
            }
#pragma unroll
            for (int j = 0; j < 4; j++) {
                uint32_t boff = (uint32_t)((wc * 32 + 8 * j + (lane & 7)) * (MMS * 2)
                                           + ks * 32 + ((lane >> 3) & 1) * 16);
                uint32_t bhi[2], blo[2];
                ldsm_x2(bhi, sBhi + boff);
                ldsm_x2(blo, sBlo + boff);
#pragma unroll
                for (int i = 0; i < 2; i++) {
                    mma_bf16(acc[i][j], ahi[i], bhi);
                    mma_bf16(acc[i][j], ahi[i], blo);
                    mma_bf16(acc[i][j], alo[i], bhi);
                }
            }
        }
        __syncthreads();
    }

    const int gm = m0 + wr * 32;
    const int gn = n0 + wc * 32;
#pragma unroll
    for (int i = 0; i < 2; i++) {
#pragma unroll
        for (int j = 0; j < 4; j++) {
            int r = gm + 16 * i + (lane >> 2);
            int c = gn + 8 * j + 2 * (lane & 3);
            float2 bv = *reinterpret_cast<const float2*>(bias + c);
            float2 v0 = {acc[i][j][0] + bv.x, acc[i][j][1] + bv.y};
            float2 v1 = {acc[i][j][2] + bv.x, acc[i][j][3] + bv.y};
            *reinterpret_cast<float2*>(g_qkv + (size_t)r * TD + c)       = v0;
            *reinterpret_cast<float2*>(g_qkv + (size_t)(r + 8) * TD + c) = v1;
        }
    }
}

// ---------------------------------------------------------------------------
// Kernel 2: scores + causal/pad mask + softmax -> attn_weights.
// NEW SHAPE: 2 rows/warp, 32-row chunks, pairs {p, 15-p} (each sums to 5
// key-block passes). __launch_bounds__(512, 2) -> 2 blocks/SM resident.
// ---------------------------------------------------------------------------
__global__ __launch_bounds__(512, 2) void attn_kernel(
    const unsigned char* __restrict__ mask,
    float* __restrict__ wout,
    int b0)
{
    __shared__ __align__(16) float Kt[HD][516];     // 33 KB
    __shared__ __align__(16) ull   Qsu[32][HD];     // 4 KB
    __shared__ __align__(4) unsigned char pm[SS];

    const int p = blockIdx.x;        // 0..7
    const int h = blockIdx.y;
    const int b = b0 + blockIdx.z;
    const int t = threadIdx.x;

    const int cA = p;                // chunks of 32 rows
    const int cB = 15 - p;
    const int njbB  = (32 * cB + 159) >> 7;   // 3 or 4
    const int kmaxL = njbB << 7;

    const float* kbase = g_qkv + (size_t)b * SS * TD + DD + h * HD;
    for (int idx = t; idx < kmaxL * 4; idx += 512) {
        int key = idx >> 2;
        int dq  = (idx & 3) * 4;
        float4 kv = *reinterpret_cast<const float4*>(kbase + (size_t)key * TD + dq);
        Kt[dq + 0][key] = kv.x;
        Kt[dq + 1][key] = kv.y;
        Kt[dq + 2][key] = kv.z;
        Kt[dq + 3][key] = kv.w;
    }
    if (t < kmaxL) pm[t] = mask[b * SS + t];
    __syncthreads();

    const int wd    = t >> 5;        // 0..15
    const int lane  = t & 31;
    const int rbase = 2 * wd;        // 2 rows per warp

#pragma unroll
    for (int ci = 0; ci < 2; ci++) {
        const int qc  = (ci == 0) ? cA : cB;
        const int q0  = qc * 32;
        const int njb = (32 * qc + 159) >> 7;

        if (t < 128) {
            int row = t >> 2;
            int dq  = (t & 3) * 4;
            float4 qv = *reinterpret_cast<const float4*>(
                g_qkv + (size_t)(b * SS + q0 + row) * TD + h * HD + dq);
            Qsu[row][dq + 0] = pack2(qv.x, qv.x);
            Qsu[row][dq + 1] = pack2(qv.y, qv.y);
            Qsu[row][dq + 2] = pack2(qv.z, qv.z);
            Qsu[row][dq + 3] = pack2(qv.w, qv.w);
        }
        __syncthreads();

        ull s2[2][2][4];
#pragma unroll
        for (int r = 0; r < 2; r++)
#pragma unroll
            for (int pp = 0; pp < 2; pp++)
#pragma unroll
                for (int jb = 0; jb < 4; jb++) s2[r][pp][jb] = 0ULL;

#pragma unroll
        for (int d = 0; d < HD; d++) {
            ull q2[2];
            q2[0] = Qsu[rbase + 0][d];
            q2[1] = Qsu[rbase + 1][d];
#pragma unroll
            for (int jb = 0; jb < 4; jb++) {
                if (jb < njb) {
                    ulonglong2 kp = *reinterpret_cast<const ulonglong2*>(
                        &Kt[d][4 * lane + 128 * jb]);
#pragma unroll
                    for (int r = 0; r < 2; r++) {
                        s2[r][0][jb] = fma2(q2[r], kp.x, s2[r][0][jb]);
                        s2[r][1][jb] = fma2(q2[r], kp.y, s2[r][1][jb]);
                    }
                }
            }
        }

#pragma unroll
        for (int r = 0; r < 2; r++) {
            const int rg = q0 + rbase + r;
            float v[16];
            float sum = 0.f;
#pragma unroll
            for (int jb = 0; jb < 4; jb++) {
                if (jb < njb) {
                    int kb = 4 * lane + 128 * jb;
                    uchar4 pmv = *reinterpret_cast<const uchar4*>(&pm[kb]);
                    float f0, f1, f2, f3;
                    unpack2(s2[r][0][jb], f0, f1);
                    unpack2(s2[r][1][jb], f2, f3);
                    float e0 = (kb + 0 > rg || pmv.x) ? 0.f : __expf(f0 * 0.25f);
                    float e1 = (kb + 1 > rg || pmv.y) ? 0.f : __expf(f1 * 0.25f);
                    float e2 = (kb + 2 > rg || pmv.z) ? 0.f : __expf(f2 * 0.25f);
                    float e3 = (kb + 3 > rg || pmv.w) ? 0.f : __expf(f3 * 0.25f);
                    v[jb * 4 + 0] = e0; v[jb * 4 + 1] = e1;
                    v[jb * 4 + 2] = e2; v[jb * 4 + 3] = e3;
                    sum += (e0 + e1) + (e2 + e3);
                }
            }
#pragma unroll
            for (int off = 16; off > 0; off >>= 1)
                sum += __shfl_xor_sync(0xffffffffu, sum, off);
            float inv = 1.f / sum;

            float4* orow = reinterpret_cast<float4*>(
                wout + (((size_t)(b * HH + h) * SS + rg) * SS));
#pragma unroll
            for (int jb = 0; jb < 4; jb++) {
                float4 o;
                if (jb < njb) {
                    o.x = v[jb * 4 + 0] * inv;
                    o.y = v[jb * 4 + 1] * inv;
                    o.z = v[jb * 4 + 2] * inv;
                    o.w = v[jb * 4 + 3] * inv;
                } else {
                    o.x = 0.f; o.y = 0.f; o.z = 0.f; o.w = 0.f;
                }
                __stcs(orow + lane + 32 * jb, o);
            }
        }
        __syncthreads();
    }
}

// ---------------------------------------------------------------------------
// Kernel 3a: attnv computes softmax(q_last·K^T/4)·V directly from qkv.
// ---------------------------------------------------------------------------
__global__ __launch_bounds__(256) void attnv_kernel(
    const unsigned char* __restrict__ mask,
    int b0)
{
    __shared__ float esm[SS];
    __shared__ float qsm[HD];
    __shared__ float red[256];
    __shared__ int s_last;

    const int h = blockIdx.x;
    const int b = b0 + blockIdx.y;
    const int t = threadIdx.x;

    int cnt = 0;
    for (int s = t; s < SS; s += 256) cnt += (mask[b * SS + s] == 0) ? 1 : 0;
    red[t] = (float)cnt;
    __syncthreads();
#pragma unroll
    for (int off = 128; off > 0; off >>= 1) {
        if (t < off) red[t] += red[t + off];
        __syncthreads();
    }
    if (t == 0) {
        int len = (int)(red[0] + 0.5f);
        s_last = (len > 0) ? (len - 1) : 0;
    }
    __syncthreads();
    const int last = s_last;

    if (t < HD)
        qsm[t] = g_qkv[(size_t)(b * SS + last) * TD + h * HD + t];
    __syncthreads();

    const float* kb = g_qkv + (size_t)b * SS * TD + DD + h * HD;
    float psum = 0.f;
#pragma unroll
    for (int u = 0; u < 2; u++) {
        int k = t + 256 * u;
        const float4* kr = reinterpret_cast<const float4*>(kb + (size_t)k * TD);
        float s = 0.f;
#pragma unroll
        for (int dq = 0; dq < 4; dq++) {
            float4 kv = kr[dq];
            s += qsm[dq * 4 + 0] * kv.x + qsm[dq * 4 + 1] * kv.y
               + qsm[dq * 4 + 2] * kv.z + qsm[dq * 4 + 3] * kv.w;
        }
        bool pad = (mask[b * SS + k] != 0);
        float e = (k > last || pad) ? 0.f : __expf(s * 0.25f);
        esm[k] = e;
        psum += e;
    }
    red[t] = psum;
    __syncthreads();
#pragma unroll
    for (int off = 128; off > 0; off >>= 1) {
        if (t < off) red[t] += red[t + off];
        __syncthreads();
    }
    const float inv = 1.f / red[0];
    __syncthreads();

    const int d  = t & 15;
    const int kg = t >> 4;
    const float* vb = g_qkv + (size_t)b * SS * TD + 2 * DD + h * HD + d;
    float a0 = 0.f, a1 = 0.f;
#pragma unroll 8
    for (int j = 0; j < 32; j += 2) {
        int k0 = kg + 16 * j;
        int k1 = kg + 16 * (j + 1);
        a0 = fmaf(esm[k0], vb[(size_t)k0 * TD], a0);
        a1 = fmaf(esm[k1], vb[(size_t)k1 * TD], a1);
    }
    red[t] = a0 + a1;
    __syncthreads();
#pragma unroll
    for (int off = 128; off >= 16; off >>= 1) {
        if (t < off) red[t] += red[t + off];
        __syncthreads();
    }
    if (t < 16) g_av[b * DD + h * HD + t] = red[t] * inv;
}

// ---------------------------------------------------------------------------
// Kernel 3b/3c: y[b,j] = x[b,:] @ w[j,:] + bias[j]
// ---------------------------------------------------------------------------
__global__ __launch_bounds__(256) void mv_kernel(
    const float* __restrict__ x,
    const float* __restrict__ w,
    const float* __restrict__ bias,
    float* __restrict__ y,
    int b0)
{
    __shared__ __align__(16) float xs[DD];

    const int jc = blockIdx.x;
    const int b  = b0 + blockIdx.y;
    const int t  = threadIdx.x;
    const int wd = t >> 5, lane = t & 31;

    xs[t] = x[b * DD + t];
    __syncthreads();

    const float4* xp = reinterpret_cast<const float4*>(xs);
    float4 x0 = xp[lane * 2], x1 = xp[lane * 2 + 1];
#pragma unroll
    for (int jj = 0; jj < 4; jj++) {
        int j = jc * 32 + wd * 4 + jj;
        const float4* wr = reinterpret_cast<const float4*>(w + (size_t)j * DD);
        float4 w0 = wr[lane * 2], w1 = wr[lane * 2 + 1];
        float acc = x0.x * w0.x + x0.y * w0.y + x0.z * w0.z + x0.w * w0.w
                  + x1.x * w1.x + x1.y * w1.y + x1.z * w1.z + x1.w * w1.w;
#pragma unroll
        for (int off = 16; off > 0; off >>= 1)
            acc += __shfl_xor_sync(0xffffffffu, acc, off);
        if (lane == 0) y[b * DD + j] = acc + bias[j];
    }
}

// ---------------------------------------------------------------------------
// Kernel 3d: LN + ReLU + L2 normalize
// ---------------------------------------------------------------------------
__device__ __forceinline__ float block_reduce_sum(float v, float* red, int t) {
    red[t] = v;
    __syncthreads();
#pragma unroll
    for (int off = 128; off > 0; off >>= 1) {
        if (t < off) red[t] += red[t + off];
        __syncthreads();
    }
    float r = red[0];
    __syncthreads();
    return r;
}

__global__ __launch_bounds__(256) void ln_kernel(
    const float* __restrict__ lng, const float* __restrict__ lnb,
    float* __restrict__ user,
    int b0)
{
    __shared__ float red[256];
    const int b = b0 + blockIdx.x;
    const int t = threadIdx.x;

    float hv = g_h2[b * DD + t];
    float mu = block_reduce_sum(hv, red, t) * (1.0f / DD);
    float c  = hv - mu;
    float var = block_reduce_sum(c * c, red, t) * (1.0f / DD);
    float y = c * rsqrtf(var + 1e-5f) * lng[t] + lnb[t];
    y = fmaxf(y, 0.f);

    float ss = block_reduce_sum(y * y, red, t);
    float norm = sqrtf(ss);
    float denom = fmaxf(norm, 1e-12f);
    user[b * DD + t] = y / denom;
}

// ---------------------------------------------------------------------------
extern "C" void kernel_launch(void* const* d_in, const int* in_sizes, int n_in,
                              void* d_out, int out_size) {
    const float*         news  = (const float*)d_in[0];
    const unsigned char* mask  = (const unsigned char*)d_in[1];
    const float*         pos   = (const float*)d_in[2];
    const float*         inw   = (const float*)d_in[3];
    const float*         inb   = (const float*)d_in[4];
    const float*         outw  = (const float*)d_in[5];
    const float*         outb  = (const float*)d_in[6];
    const float*         projw = (const float*)d_in[7];
    const float*         projb = (const float*)d_in[8];
    const float*         lng   = (const float*)d_in[9];
    const float*         lnb   = (const float*)d_in[10];

    float* user = (float*)d_out;
    float* wout = (float*)d_out + (BB * DD);

    float* g_av_p;  cudaGetSymbolAddress((void**)&g_av_p,  g_av);
    float* g_h1_p;  cudaGetSymbolAddress((void**)&g_h1_p,  g_h1);
    float* g_h2_p;  cudaGetSymbolAddress((void**)&g_h2_p,  g_h2);

    static const int NSTREAM = 4;
    static cudaStream_t st[NSTREAM] = {};
    static cudaEvent_t evFork = nullptr;
    static cudaEvent_t evJoin[NSTREAM] = {};
    if (st[1] == nullptr) {
        for (int i = 1; i < NSTREAM; i++)
            cudaStreamCreateWithFlags(&st[i], cudaStreamNonBlocking);
        cudaEventCreateWithFlags(&evFork, cudaEventDisableTiming);
        for (int i = 1; i < NSTREAM; i++)
            cudaEventCreateWithFlags(&evJoin[i], cudaEventDisableTiming);
        cudaFuncSetAttribute(qkv_mma_kernel,
                             cudaFuncAttributeMaxDynamicSharedMemorySize, SMEM_MMA);
    }

    const int BPQ = BB / NSTREAM;          // 4 batches per stream
    const int QROWS = BPQ * SS;            // 2048 rows per quarter

    // bf16 hi/lo conversion (x and w) — before fork.
    prep_kernel<<<BB * SS + TD, 256>>>(news, pos, inw);

    cudaEventRecord(evFork, 0);
    for (int i = 1; i < NSTREAM; i++) cudaStreamWaitEvent(st[i], evFork, 0);

    for (int i = 0; i < NSTREAM; i++) {
        cudaStream_t s = (i == 0) ? (cudaStream_t)0 : st[i];
        int b0 = i * BPQ;
        dim3 qgrid(TD / 128, QROWS / 128);
        qkv_mma_kernel<<<qgrid, 512, SMEM_MMA, s>>>(inb, b0 * SS);

        dim3 agrid(8, HH, BPQ);
        attn_kernel<<<agrid, 512, 0, s>>>(mask, wout, b0);

        dim3 vgrid(HH, BPQ);
        attnv_kernel<<<vgrid, 256, 0, s>>>(mask, b0);
        dim3 mgrid(8, BPQ);
        mv_kernel<<<mgrid, 256, 0, s>>>(g_av_p, outw, outb, g_h1_p, b0);
        mv_kernel<<<mgrid, 256, 0, s>>>(g_h1_p, projw, projb, g_h2_p, b0);
        ln_kernel<<<BPQ, 256, 0, s>>>(lng, lnb, user, b0);
    }
    for (int i = 1; i < NSTREAM; i++) {
        cudaEventRecord(evJoin[i], st[i]);
        cudaStreamWaitEvent(0, evJoin[i], 0);
    }
}